// round 1
// baseline (speedup 1.0000x reference)
#include <cuda_runtime.h>
#include <cuda_bf16.h>

// ---------------------------------------------------------------------------
// MultiViewSelfAttention: VIEW=8, SEQ=2048, HID=1024, ATT=128
//   qh = (q @ wq + bq) * A^-0.5 ; kh = k @ wk + bk ; vh = v @ wv + bv
//   P  = softmax(qh @ kh^T) + bias      (bias AFTER softmax!)
//   x  = P @ vh  -> [S, V*A] ; out = x @ wo + bo  -> [2048, 1024] fp32
// Round 0: fp32 register-tiled GEMMs + fused softmax/bias pass. Baseline.
// ---------------------------------------------------------------------------

#define VIEW 8
#define SEQ  2048
#define HID  1024
#define ATT  128

// Scratch (allocation-free rule: __device__ globals)
__device__ float g_qh[VIEW * SEQ * ATT];     // 8 MB
__device__ float g_kh[VIEW * SEQ * ATT];     // 8 MB
__device__ float g_vh[VIEW * SEQ * ATT];     // 8 MB
__device__ float g_P [(long)VIEW * SEQ * SEQ]; // 128 MB
__device__ float g_x [SEQ * (VIEW * ATT)];   // 8 MB

// ---------------------------------------------------------------------------
// Generic fp32 GEMM:  C = alpha * (A @ B + bias_rowvec)
//   A: [M,K] row-major, ld = lda
//   B: BT ? [N,K] row-major (ld = ldb=K)  :  [K,N] row-major (ld = ldb)
//   C: row-major, ld = ldc
//   Per-z batch strides sA/sB/sC (elements). 256 threads, TM x TN microtile.
//   All extents assumed divisible by tile sizes (true for every call below).
// ---------------------------------------------------------------------------
template<int BM, int BN, int BK, int TM, int TN, bool BT>
__global__ void gemm_k(const float* __restrict__ A,
                       const float* __restrict__ B,
                       const float* __restrict__ bias,
                       float* __restrict__ C,
                       int lda, int ldb, int ldc,
                       long sA, long sB, long sC,
                       int K, float alpha)
{
    constexpr int TX = BN / TN;
    constexpr int TY = BM / TM;
    static_assert(TX * TY == 256, "need 256 threads");
    constexpr int KB4 = BK / 4;
    constexpr int NB4 = BN / 4;
    constexpr int LA = (BM * BK) / (4 * 256);
    constexpr int LB = (BN * BK) / (4 * 256);
    static_assert(LA >= 1 && LB >= 1, "tile too small for f4 loads");

    __shared__ float As[BK][BM];
    __shared__ float Bs[BK][BN];

    const int tid = threadIdx.x;
    const int tx  = tid % TX;
    const int ty  = tid / TX;
    const int m0  = blockIdx.y * BM;
    const int n0  = blockIdx.x * BN;

    A += (long)blockIdx.z * sA;
    B += (long)blockIdx.z * sB;
    C += (long)blockIdx.z * sC;

    float acc[TM][TN];
#pragma unroll
    for (int i = 0; i < TM; i++)
#pragma unroll
        for (int j = 0; j < TN; j++) acc[i][j] = 0.f;

    for (int k0 = 0; k0 < K; k0 += BK) {
        // --- load A tile (transpose into As[k][m]) ---
#pragma unroll
        for (int i = 0; i < LA; i++) {
            int idx = tid + i * 256;
            int row = idx / KB4;       // m within tile
            int c4  = idx % KB4;       // float4 index along K
            float4 v = *reinterpret_cast<const float4*>(
                A + (long)(m0 + row) * lda + k0 + c4 * 4);
            As[c4 * 4 + 0][row] = v.x;
            As[c4 * 4 + 1][row] = v.y;
            As[c4 * 4 + 2][row] = v.z;
            As[c4 * 4 + 3][row] = v.w;
        }
        // --- load B tile ---
        if (BT) {
#pragma unroll
            for (int i = 0; i < LB; i++) {
                int idx = tid + i * 256;
                int row = idx / KB4;   // n within tile
                int c4  = idx % KB4;   // float4 index along K
                float4 v = *reinterpret_cast<const float4*>(
                    B + (long)(n0 + row) * ldb + k0 + c4 * 4);
                Bs[c4 * 4 + 0][row] = v.x;
                Bs[c4 * 4 + 1][row] = v.y;
                Bs[c4 * 4 + 2][row] = v.z;
                Bs[c4 * 4 + 3][row] = v.w;
            }
        } else {
#pragma unroll
            for (int i = 0; i < LB; i++) {
                int idx = tid + i * 256;
                int row = idx / NB4;   // k within tile
                int c4  = idx % NB4;   // float4 index along N
                float4 v = *reinterpret_cast<const float4*>(
                    B + (long)(k0 + row) * ldb + n0 + c4 * 4);
                *reinterpret_cast<float4*>(&Bs[row][c4 * 4]) = v;
            }
        }
        __syncthreads();

#pragma unroll
        for (int kk = 0; kk < BK; kk++) {
            float ra[TM], rb[TN];
#pragma unroll
            for (int i = 0; i < TM; i++) ra[i] = As[kk][ty * TM + i];
#pragma unroll
            for (int j = 0; j < TN; j++) rb[j] = Bs[kk][tx * TN + j];
#pragma unroll
            for (int i = 0; i < TM; i++)
#pragma unroll
                for (int j = 0; j < TN; j++) acc[i][j] += ra[i] * rb[j];
        }
        __syncthreads();
    }

    // epilogue
#pragma unroll
    for (int i = 0; i < TM; i++) {
        long crow = (long)(m0 + ty * TM + i) * ldc;
#pragma unroll
        for (int j = 0; j < TN; j++) {
            int n = n0 + tx * TN + j;
            float b = bias ? bias[n] : 0.f;
            C[crow + n] = alpha * (acc[i][j] + b);
        }
    }
}

// ---------------------------------------------------------------------------
// Row softmax in-place + post-softmax bias add.
// One block per row (V*S = 16384 rows of length 2048). 256 threads x 8 elems.
// ---------------------------------------------------------------------------
__global__ void softmax_bias_k(float* __restrict__ P,
                               const float* __restrict__ bias)
{
    const long r = blockIdx.x;
    float* row = P + r * (long)SEQ;
    const float* brow = bias + r * (long)SEQ;
    const int tid  = threadIdx.x;
    const int lane = tid & 31;
    const int wid  = tid >> 5;

    __shared__ float sred[8];

    float4 v0 = *reinterpret_cast<const float4*>(row + tid * 4);
    float4 v1 = *reinterpret_cast<const float4*>(row + 1024 + tid * 4);

    // --- row max ---
    float m = fmaxf(fmaxf(fmaxf(v0.x, v0.y), fmaxf(v0.z, v0.w)),
                    fmaxf(fmaxf(v1.x, v1.y), fmaxf(v1.z, v1.w)));
#pragma unroll
    for (int off = 16; off > 0; off >>= 1)
        m = fmaxf(m, __shfl_xor_sync(0xFFFFFFFFu, m, off));
    if (lane == 0) sred[wid] = m;
    __syncthreads();
    float rowmax = sred[0];
#pragma unroll
    for (int j = 1; j < 8; j++) rowmax = fmaxf(rowmax, sred[j]);
    __syncthreads();   // protect sred before reuse

    // --- exp + row sum ---
    v0.x = __expf(v0.x - rowmax); v0.y = __expf(v0.y - rowmax);
    v0.z = __expf(v0.z - rowmax); v0.w = __expf(v0.w - rowmax);
    v1.x = __expf(v1.x - rowmax); v1.y = __expf(v1.y - rowmax);
    v1.z = __expf(v1.z - rowmax); v1.w = __expf(v1.w - rowmax);
    float s = (v0.x + v0.y + v0.z + v0.w) + (v1.x + v1.y + v1.z + v1.w);
#pragma unroll
    for (int off = 16; off > 0; off >>= 1)
        s += __shfl_xor_sync(0xFFFFFFFFu, s, off);
    if (lane == 0) sred[wid] = s;
    __syncthreads();
    float rowsum = 0.f;
#pragma unroll
    for (int j = 0; j < 8; j++) rowsum += sred[j];
    const float inv = 1.f / rowsum;

    // --- normalize + post-softmax bias, store ---
    float4 b0 = *reinterpret_cast<const float4*>(brow + tid * 4);
    float4 b1 = *reinterpret_cast<const float4*>(brow + 1024 + tid * 4);
    v0.x = v0.x * inv + b0.x; v0.y = v0.y * inv + b0.y;
    v0.z = v0.z * inv + b0.z; v0.w = v0.w * inv + b0.w;
    v1.x = v1.x * inv + b1.x; v1.y = v1.y * inv + b1.y;
    v1.z = v1.z * inv + b1.z; v1.w = v1.w * inv + b1.w;
    *reinterpret_cast<float4*>(row + tid * 4)        = v0;
    *reinterpret_cast<float4*>(row + 1024 + tid * 4) = v1;
}

// ---------------------------------------------------------------------------
extern "C" void kernel_launch(void* const* d_in, const int* in_sizes, int n_in,
                              void* d_out, int out_size)
{
    const float* q    = (const float*)d_in[0];
    const float* k    = (const float*)d_in[1];
    const float* v    = (const float*)d_in[2];
    const float* bias = (const float*)d_in[3];
    const float* wq   = (const float*)d_in[4];
    const float* bq   = (const float*)d_in[5];
    const float* wk   = (const float*)d_in[6];
    const float* bk   = (const float*)d_in[7];
    const float* wv   = (const float*)d_in[8];
    const float* bv   = (const float*)d_in[9];
    const float* wo   = (const float*)d_in[10];
    const float* bo   = (const float*)d_in[11];
    float* out = (float*)d_out;

    float *qh, *kh, *vh, *P, *x;
    cudaGetSymbolAddress((void**)&qh, g_qh);
    cudaGetSymbolAddress((void**)&kh, g_kh);
    cudaGetSymbolAddress((void**)&vh, g_vh);
    cudaGetSymbolAddress((void**)&P,  g_P);
    cudaGetSymbolAddress((void**)&x,  g_x);

    const float scale = 0.088388347648318447f;  // ATT^-0.5

    // 1-3) projections: [16384,1024] @ [1024,128] + b
    gemm_k<64, 128, 16, 8, 4, false><<<dim3(1, (VIEW * SEQ) / 64, 1), 256>>>(
        q, wq, bq, qh, HID, ATT, ATT, 0, 0, 0, HID, scale);
    gemm_k<64, 128, 16, 8, 4, false><<<dim3(1, (VIEW * SEQ) / 64, 1), 256>>>(
        k, wk, bk, kh, HID, ATT, ATT, 0, 0, 0, HID, 1.f);
    gemm_k<64, 128, 16, 8, 4, false><<<dim3(1, (VIEW * SEQ) / 64, 1), 256>>>(
        v, wv, bv, vh, HID, ATT, ATT, 0, 0, 0, HID, 1.f);

    // 4) scores: per view, S = qh @ kh^T   [2048,2048], NT
    gemm_k<128, 64, 32, 8, 4, true><<<dim3(SEQ / 64, SEQ / 128, VIEW), 256>>>(
        qh, kh, nullptr, P, ATT, ATT, SEQ,
        (long)SEQ * ATT, (long)SEQ * ATT, (long)SEQ * SEQ, ATT, 1.f);

    // 5) softmax rows + post-softmax bias (in-place on P)
    softmax_bias_k<<<VIEW * SEQ, 256>>>(P, bias);

    // 6) x = P @ vh, scattered into [S, V*A] (per-view column offset z*128)
    gemm_k<128, 64, 16, 8, 4, false><<<dim3(ATT / 64, SEQ / 128, VIEW), 256>>>(
        P, vh, nullptr, x, SEQ, ATT, VIEW * ATT,
        (long)SEQ * SEQ, (long)SEQ * ATT, (long)ATT, SEQ, 1.f);

    // 7) out = x @ wo + bo   [2048,1024]
    gemm_k<128, 64, 16, 8, 4, false><<<dim3(HID / 64, SEQ / 128, 1), 256>>>(
        x, wo, bo, out, VIEW * ATT, HID, HID, 0, 0, 0, VIEW * ATT, 1.f);
}

// round 2
// speedup vs baseline: 1.8695x; 1.8695x over previous
#include <cuda_runtime.h>
#include <cuda_bf16.h>
#include <cstdint>

// ---------------------------------------------------------------------------
// MultiViewSelfAttention: VIEW=8, SEQ=2048, HID=1024, ATT=128
// Round 1: all GEMMs on TF32 tensor cores (mma.sync m16n8k8), fused softmax.
// ---------------------------------------------------------------------------

#define VIEW 8
#define SEQ  2048
#define HID  1024
#define ATT  128

__device__ float g_qh[VIEW * SEQ * ATT];
__device__ float g_kh[VIEW * SEQ * ATT];
__device__ float g_vh[VIEW * SEQ * ATT];
__device__ float g_P [(long)VIEW * SEQ * SEQ];
__device__ float g_x [SEQ * (VIEW * ATT)];

__device__ __forceinline__ float to_tf32(float x) {
    float y;
    asm("cvt.rna.tf32.f32 %0, %1;" : "=f"(y) : "f"(x));
    return y;
}

__device__ __forceinline__ void mma_tf32(float c[4], const uint32_t a[4],
                                         const uint32_t b[2]) {
    asm volatile(
        "mma.sync.aligned.m16n8k8.row.col.f32.tf32.tf32.f32 "
        "{%0,%1,%2,%3}, {%4,%5,%6,%7}, {%8,%9}, {%0,%1,%2,%3};"
        : "+f"(c[0]), "+f"(c[1]), "+f"(c[2]), "+f"(c[3])
        : "r"(a[0]), "r"(a[1]), "r"(a[2]), "r"(a[3]), "r"(b[0]), "r"(b[1]));
}

// ---------------------------------------------------------------------------
// TF32 tensor-core GEMM:  C = alpha * (A @ B + bias_rowvec)
//   A: [M,K] row-major.  B: BT ? [N,K] row-major : [K,N] row-major.
//   256 threads = 8 warps as 4x2. Warp tile (BM/4) x (BN/2). BK=16.
//   All extents divisible by tiles (true for every call site).
// ---------------------------------------------------------------------------
template<int BM, int BN, bool BT>
__global__ __launch_bounds__(256)
void gemm_tc(const float* __restrict__ A,
             const float* __restrict__ B,
             const float* __restrict__ bias,
             float* __restrict__ C,
             int lda, int ldb, int ldc,
             long sA, long sB, long sC,
             int K, float alpha)
{
    constexpr int BK  = 16;
    constexpr int PAD = 4;                 // smem row stride 20 -> conflict-free frags
    constexpr int MT  = BM / 64;           // m16 tiles per warp (4 warps along M)
    constexpr int NT  = BN / 16;           // n8  tiles per warp (2 warps along N)
    constexpr int LA  = (BM * BK) / (4 * 256);
    constexpr int LB  = (BN * BK) / (4 * 256);

    __shared__ float As[BM][BK + PAD];
    __shared__ float Bs[BN][BK + PAD];

    const int tid  = threadIdx.x;
    const int warp = tid >> 5;
    const int lane = tid & 31;
    const int wm   = warp >> 1;            // 0..3
    const int wn   = warp & 1;             // 0..1
    const int m_off = wm * (MT * 16);
    const int n_off = wn * (NT * 8);
    const int lr = lane >> 2;              // 0..7
    const int lc = lane & 3;               // 0..3

    const int m0 = blockIdx.y * BM;
    const int n0 = blockIdx.x * BN;

    A += (long)blockIdx.z * sA;
    B += (long)blockIdx.z * sB;
    C += (long)blockIdx.z * sC;

    float acc[MT][NT][4];
#pragma unroll
    for (int i = 0; i < MT; i++)
#pragma unroll
        for (int j = 0; j < NT; j++)
#pragma unroll
            for (int t = 0; t < 4; t++) acc[i][j][t] = 0.f;

    for (int k0 = 0; k0 < K; k0 += BK) {
        // --- stage A tile: As[m][k] ---
#pragma unroll
        for (int i = 0; i < LA; i++) {
            int idx = tid + i * 256;
            int m   = idx >> 2;
            int k4  = (idx & 3) * 4;
            float4 g = *reinterpret_cast<const float4*>(
                A + (long)(m0 + m) * lda + k0 + k4);
            As[m][k4 + 0] = to_tf32(g.x);
            As[m][k4 + 1] = to_tf32(g.y);
            As[m][k4 + 2] = to_tf32(g.z);
            As[m][k4 + 3] = to_tf32(g.w);
        }
        // --- stage B tile: Bs[n][k] ---
        if (BT) {
#pragma unroll
            for (int i = 0; i < LB; i++) {
                int idx = tid + i * 256;
                int n   = idx >> 2;
                int k4  = (idx & 3) * 4;
                float4 g = *reinterpret_cast<const float4*>(
                    B + (long)(n0 + n) * ldb + k0 + k4);
                Bs[n][k4 + 0] = to_tf32(g.x);
                Bs[n][k4 + 1] = to_tf32(g.y);
                Bs[n][k4 + 2] = to_tf32(g.z);
                Bs[n][k4 + 3] = to_tf32(g.w);
            }
        } else {
#pragma unroll
            for (int i = 0; i < LB; i++) {
                int idx = tid + i * 256;
                int k   = idx / (BN / 4);
                int n4  = (idx % (BN / 4)) * 4;
                float4 g = *reinterpret_cast<const float4*>(
                    B + (long)(k0 + k) * ldb + n0 + n4);
                Bs[n4 + 0][k] = to_tf32(g.x);
                Bs[n4 + 1][k] = to_tf32(g.y);
                Bs[n4 + 2][k] = to_tf32(g.z);
                Bs[n4 + 3][k] = to_tf32(g.w);
            }
        }
        __syncthreads();

        // --- two k8 steps ---
#pragma unroll
        for (int ks = 0; ks < 2; ks++) {
            const int kb = ks * 8;
            uint32_t af[MT][4], bf[NT][2];
#pragma unroll
            for (int mi = 0; mi < MT; mi++) {
                const int r = m_off + mi * 16 + lr;
                af[mi][0] = __float_as_uint(As[r    ][kb + lc    ]);
                af[mi][1] = __float_as_uint(As[r + 8][kb + lc    ]);
                af[mi][2] = __float_as_uint(As[r    ][kb + lc + 4]);
                af[mi][3] = __float_as_uint(As[r + 8][kb + lc + 4]);
            }
#pragma unroll
            for (int ni = 0; ni < NT; ni++) {
                const int n = n_off + ni * 8 + lr;
                bf[ni][0] = __float_as_uint(Bs[n][kb + lc    ]);
                bf[ni][1] = __float_as_uint(Bs[n][kb + lc + 4]);
            }
#pragma unroll
            for (int mi = 0; mi < MT; mi++)
#pragma unroll
                for (int ni = 0; ni < NT; ni++)
                    mma_tf32(acc[mi][ni], af[mi], bf[ni]);
        }
        __syncthreads();
    }

    // --- epilogue ---
#pragma unroll
    for (int mi = 0; mi < MT; mi++) {
#pragma unroll
        for (int ni = 0; ni < NT; ni++) {
            const int row = m0 + m_off + mi * 16 + lr;
            const int col = n0 + n_off + ni * 8 + lc * 2;
            float b0 = bias ? bias[col]     : 0.f;
            float b1 = bias ? bias[col + 1] : 0.f;
            float2 v0 = make_float2(alpha * (acc[mi][ni][0] + b0),
                                    alpha * (acc[mi][ni][1] + b1));
            float2 v1 = make_float2(alpha * (acc[mi][ni][2] + b0),
                                    alpha * (acc[mi][ni][3] + b1));
            *reinterpret_cast<float2*>(C + (long)row * ldc + col)       = v0;
            *reinterpret_cast<float2*>(C + (long)(row + 8) * ldc + col) = v1;
        }
    }
}

// ---------------------------------------------------------------------------
// Row softmax in-place + post-softmax bias add (unchanged from R0).
// ---------------------------------------------------------------------------
__global__ void softmax_bias_k(float* __restrict__ P,
                               const float* __restrict__ bias)
{
    const long r = blockIdx.x;
    float* row = P + r * (long)SEQ;
    const float* brow = bias + r * (long)SEQ;
    const int tid  = threadIdx.x;
    const int lane = tid & 31;
    const int wid  = tid >> 5;

    __shared__ float sred[8];

    float4 v0 = *reinterpret_cast<const float4*>(row + tid * 4);
    float4 v1 = *reinterpret_cast<const float4*>(row + 1024 + tid * 4);

    float m = fmaxf(fmaxf(fmaxf(v0.x, v0.y), fmaxf(v0.z, v0.w)),
                    fmaxf(fmaxf(v1.x, v1.y), fmaxf(v1.z, v1.w)));
#pragma unroll
    for (int off = 16; off > 0; off >>= 1)
        m = fmaxf(m, __shfl_xor_sync(0xFFFFFFFFu, m, off));
    if (lane == 0) sred[wid] = m;
    __syncthreads();
    float rowmax = sred[0];
#pragma unroll
    for (int j = 1; j < 8; j++) rowmax = fmaxf(rowmax, sred[j]);
    __syncthreads();

    v0.x = __expf(v0.x - rowmax); v0.y = __expf(v0.y - rowmax);
    v0.z = __expf(v0.z - rowmax); v0.w = __expf(v0.w - rowmax);
    v1.x = __expf(v1.x - rowmax); v1.y = __expf(v1.y - rowmax);
    v1.z = __expf(v1.z - rowmax); v1.w = __expf(v1.w - rowmax);
    float s = (v0.x + v0.y + v0.z + v0.w) + (v1.x + v1.y + v1.z + v1.w);
#pragma unroll
    for (int off = 16; off > 0; off >>= 1)
        s += __shfl_xor_sync(0xFFFFFFFFu, s, off);
    if (lane == 0) sred[wid] = s;
    __syncthreads();
    float rowsum = 0.f;
#pragma unroll
    for (int j = 0; j < 8; j++) rowsum += sred[j];
    const float inv = 1.f / rowsum;

    float4 b0 = *reinterpret_cast<const float4*>(brow + tid * 4);
    float4 b1 = *reinterpret_cast<const float4*>(brow + 1024 + tid * 4);
    v0.x = v0.x * inv + b0.x; v0.y = v0.y * inv + b0.y;
    v0.z = v0.z * inv + b0.z; v0.w = v0.w * inv + b0.w;
    v1.x = v1.x * inv + b1.x; v1.y = v1.y * inv + b1.y;
    v1.z = v1.z * inv + b1.z; v1.w = v1.w * inv + b1.w;
    *reinterpret_cast<float4*>(row + tid * 4)        = v0;
    *reinterpret_cast<float4*>(row + 1024 + tid * 4) = v1;
}

// ---------------------------------------------------------------------------
extern "C" void kernel_launch(void* const* d_in, const int* in_sizes, int n_in,
                              void* d_out, int out_size)
{
    const float* q    = (const float*)d_in[0];
    const float* k    = (const float*)d_in[1];
    const float* v    = (const float*)d_in[2];
    const float* bias = (const float*)d_in[3];
    const float* wq   = (const float*)d_in[4];
    const float* bq   = (const float*)d_in[5];
    const float* wk   = (const float*)d_in[6];
    const float* bk   = (const float*)d_in[7];
    const float* wv   = (const float*)d_in[8];
    const float* bv   = (const float*)d_in[9];
    const float* wo   = (const float*)d_in[10];
    const float* bo   = (const float*)d_in[11];
    float* out = (float*)d_out;

    float *qh, *kh, *vh, *P, *x;
    cudaGetSymbolAddress((void**)&qh, g_qh);
    cudaGetSymbolAddress((void**)&kh, g_kh);
    cudaGetSymbolAddress((void**)&vh, g_vh);
    cudaGetSymbolAddress((void**)&P,  g_P);
    cudaGetSymbolAddress((void**)&x,  g_x);

    const float scale = 0.088388347648318447f;  // ATT^-0.5

    // 1-3) projections: [16384,1024] @ [1024,128] + b   (BN=64 -> 256 blocks)
    gemm_tc<128, 64, false><<<dim3(ATT / 64, (VIEW * SEQ) / 128, 1), 256>>>(
        q, wq, bq, qh, HID, ATT, ATT, 0, 0, 0, HID, scale);
    gemm_tc<128, 64, false><<<dim3(ATT / 64, (VIEW * SEQ) / 128, 1), 256>>>(
        k, wk, bk, kh, HID, ATT, ATT, 0, 0, 0, HID, 1.f);
    gemm_tc<128, 64, false><<<dim3(ATT / 64, (VIEW * SEQ) / 128, 1), 256>>>(
        v, wv, bv, vh, HID, ATT, ATT, 0, 0, 0, HID, 1.f);

    // 4) scores: per view  P = qh @ kh^T   [2048,2048]
    gemm_tc<128, 128, true><<<dim3(SEQ / 128, SEQ / 128, VIEW), 256>>>(
        qh, kh, nullptr, P, ATT, ATT, SEQ,
        (long)SEQ * ATT, (long)SEQ * ATT, (long)SEQ * SEQ, ATT, 1.f);

    // 5) softmax rows + post-softmax bias (in-place on P)
    softmax_bias_k<<<VIEW * SEQ, 256>>>(P, bias);

    // 6) x = P @ vh, scattered into [S, V*A]
    gemm_tc<128, 64, false><<<dim3(ATT / 64, SEQ / 128, VIEW), 256>>>(
        P, vh, nullptr, x, SEQ, ATT, VIEW * ATT,
        (long)SEQ * SEQ, (long)SEQ * ATT, (long)ATT, SEQ, 1.f);

    // 7) out = x @ wo + bo   [2048,1024]
    gemm_tc<128, 64, false><<<dim3(HID / 64, SEQ / 128, 1), 256>>>(
        x, wo, bo, out, VIEW * ATT, HID, HID, 0, 0, 0, VIEW * ATT, 1.f);
}

// round 3
// speedup vs baseline: 2.3133x; 1.2374x over previous
#include <cuda_runtime.h>
#include <cuda_bf16.h>
#include <cstdint>

// ---------------------------------------------------------------------------
// MultiViewSelfAttention: VIEW=8, SEQ=2048, HID=1024, ATT=128
// Round 2: TF32 mma.sync GEMMs with fragment-packed swizzled smem
//          (LDS.128/LDS.64 fragment loads), double buffering, 1 sync/iter.
// ---------------------------------------------------------------------------

#define VIEW 8
#define SEQ  2048
#define HID  1024
#define ATT  128

__device__ float g_qh[VIEW * SEQ * ATT];
__device__ float g_kh[VIEW * SEQ * ATT];
__device__ float g_vh[VIEW * SEQ * ATT];
__device__ float g_P [(long)VIEW * SEQ * SEQ];
__device__ float g_x [SEQ * (VIEW * ATT)];

__device__ __forceinline__ float to_tf32(float x) {
    float y;
    asm("cvt.rna.tf32.f32 %0, %1;" : "=f"(y) : "f"(x));
    return y;
}

__device__ __forceinline__ void mma_tf32(float c[4], const uint32_t a[4],
                                         const uint32_t b[2]) {
    asm volatile(
        "mma.sync.aligned.m16n8k8.row.col.f32.tf32.tf32.f32 "
        "{%0,%1,%2,%3}, {%4,%5,%6,%7}, {%8,%9}, {%0,%1,%2,%3};"
        : "+f"(c[0]), "+f"(c[1]), "+f"(c[2]), "+f"(c[3])
        : "r"(a[0]), "r"(a[1]), "r"(a[2]), "r"(a[3]), "r"(b[0]), "r"(b[1]));
}

// Fragment-packed layouts (per K-chunk of BK=16 = two k8 steps):
//  A: per (mtile of 16 rows, kstep) block of 32 lanes x 4 regs (16B units),
//     unit u = kstep*32+lane, swizzled u ^= (u>>3)&7. float addr =
//     mtile*256 + u*4 + reg.
//  B: per (ntile of 8 cols, kstep) block of 32 lanes x 2 regs (8B units),
//     global unit u8 = ntile*64 + kstep*32 + lane,
//     swizzled u8 ^= ((u8>>3)&7) ^ ((u8>>6)&15). float addr = u8*2 + reg.
__device__ __forceinline__ int a_addr(int mtile, int ks, int lane, int reg) {
    int u = ks * 32 + lane;
    u ^= (u >> 3) & 7;
    return mtile * 256 + u * 4 + reg;
}
__device__ __forceinline__ int b_addr(int ntile, int ks, int lane, int reg) {
    int u = ntile * 64 + ks * 32 + lane;
    u ^= ((u >> 3) & 7) ^ ((u >> 6) & 15);
    return u * 2 + reg;
}

// ---------------------------------------------------------------------------
// TF32 tensor-core GEMM:  C = alpha * (A @ B + bias_rowvec)
//   A: [M,K] row-major.  B: BT ? [N,K] row-major : [K,N] row-major.
//   256 threads = 8 warps as 4(m) x 2(n). BK=16. K % 16 == 0.
// ---------------------------------------------------------------------------
template<int BM, int BN, bool BT>
__global__ __launch_bounds__(256, 2)
void gemm_tc(const float* __restrict__ A,
             const float* __restrict__ B,
             const float* __restrict__ bias,
             float* __restrict__ C,
             int lda, int ldb, int ldc,
             long sA, long sB, long sC,
             int K, float alpha)
{
    constexpr int BK = 16;
    constexpr int MT = BM / 64;           // m16 tiles per warp
    constexpr int NT = BN / 16;           // n8 tiles per warp
    constexpr int LA = (BM * BK) / 1024;  // float4 loads per thread (A)
    constexpr int LB = (BN * BK) / 1024;  // float4 loads per thread (B)
    static_assert(LA >= 1 && LB >= 1, "tile too small");

    __shared__ float aF[2][BM * 16];
    __shared__ float bF[2][BN * 16];

    const int tid  = threadIdx.x;
    const int warp = tid >> 5;
    const int lane = tid & 31;
    const int wm   = warp >> 1;           // 0..3
    const int wn   = warp & 1;            // 0..1
    const int lr   = lane >> 2;
    const int lc   = lane & 3;

    const int m0 = blockIdx.y * BM;
    const int n0 = blockIdx.x * BN;

    A += (long)blockIdx.z * sA;
    B += (long)blockIdx.z * sB;
    C += (long)blockIdx.z * sC;

    float acc[MT][NT][4];
#pragma unroll
    for (int i = 0; i < MT; i++)
#pragma unroll
        for (int j = 0; j < NT; j++)
#pragma unroll
            for (int t = 0; t < 4; t++) acc[i][j][t] = 0.f;

    const int NIT = K / BK;
    float4 pa[LA], pb[LB];

    // ---- prologue: load tile 0 into registers ----
#pragma unroll
    for (int i = 0; i < LA; i++) {
        int idx = tid + i * 256;
        int r = idx >> 2, c4 = idx & 3;
        pa[i] = *reinterpret_cast<const float4*>(A + (long)(m0 + r) * lda + c4 * 4);
    }
    if (BT) {
#pragma unroll
        for (int i = 0; i < LB; i++) {
            int idx = tid + i * 256;
            int n = idx >> 2, c4 = idx & 3;
            pb[i] = *reinterpret_cast<const float4*>(B + (long)(n0 + n) * ldb + c4 * 4);
        }
    } else {
#pragma unroll
        for (int i = 0; i < LB; i++) {
            int idx = tid + i * 256;
            int kk = idx / (BN / 4), n4 = idx % (BN / 4);
            pb[i] = *reinterpret_cast<const float4*>(B + (long)kk * ldb + n0 + n4 * 4);
        }
    }

    for (int it = 0; it < NIT; ++it) {
        const int buf = it & 1;
        float* aS = aF[buf];
        float* bS = bF[buf];

        // ---- store staged registers into fragment-packed smem ----
#pragma unroll
        for (int i = 0; i < LA; i++) {
            int idx = tid + i * 256;
            int r = idx >> 2, c4 = idx & 3;
            int mtile = r >> 4, rr = r & 15;
            int ks = c4 >> 1;
            int reg = (rr >> 3) + 2 * (c4 & 1);
            float v[4] = {pa[i].x, pa[i].y, pa[i].z, pa[i].w};
#pragma unroll
            for (int j = 0; j < 4; j++)
                aS[a_addr(mtile, ks, (rr & 7) * 4 + j, reg)] = to_tf32(v[j]);
        }
        if (BT) {
#pragma unroll
            for (int i = 0; i < LB; i++) {
                int idx = tid + i * 256;
                int n = idx >> 2, c4 = idx & 3;
                int ntile = n >> 3, nn = n & 7;
                int ks = c4 >> 1, reg = c4 & 1;
                float v[4] = {pb[i].x, pb[i].y, pb[i].z, pb[i].w};
#pragma unroll
                for (int j = 0; j < 4; j++)
                    bS[b_addr(ntile, ks, nn * 4 + j, reg)] = to_tf32(v[j]);
            }
        } else {
#pragma unroll
            for (int i = 0; i < LB; i++) {
                int idx = tid + i * 256;
                int kk = idx / (BN / 4), n4 = idx % (BN / 4);
                int ks = kk >> 3, cc = kk & 7;
                int lane_c = cc & 3, reg = cc >> 2;
                float v[4] = {pb[i].x, pb[i].y, pb[i].z, pb[i].w};
#pragma unroll
                for (int j = 0; j < 4; j++) {
                    int n = n4 * 4 + j;
                    bS[b_addr(n >> 3, ks, (n & 7) * 4 + lane_c, reg)] = to_tf32(v[j]);
                }
            }
        }
        __syncthreads();

        // ---- prefetch next tile into registers (overlapped with MMAs) ----
        if (it + 1 < NIT) {
            const int k0 = (it + 1) * BK;
#pragma unroll
            for (int i = 0; i < LA; i++) {
                int idx = tid + i * 256;
                int r = idx >> 2, c4 = idx & 3;
                pa[i] = *reinterpret_cast<const float4*>(
                    A + (long)(m0 + r) * lda + k0 + c4 * 4);
            }
            if (BT) {
#pragma unroll
                for (int i = 0; i < LB; i++) {
                    int idx = tid + i * 256;
                    int n = idx >> 2, c4 = idx & 3;
                    pb[i] = *reinterpret_cast<const float4*>(
                        B + (long)(n0 + n) * ldb + k0 + c4 * 4);
                }
            } else {
#pragma unroll
                for (int i = 0; i < LB; i++) {
                    int idx = tid + i * 256;
                    int kk = idx / (BN / 4), n4 = idx % (BN / 4);
                    pb[i] = *reinterpret_cast<const float4*>(
                        B + (long)(k0 + kk) * ldb + n0 + n4 * 4);
                }
            }
        }

        // ---- MMA over the two k8 steps ----
#pragma unroll
        for (int ks = 0; ks < 2; ks++) {
            uint32_t af[MT][4], bf[NT][2];
#pragma unroll
            for (int mi = 0; mi < MT; mi++) {
                uint4 v = *reinterpret_cast<const uint4*>(
                    &aS[a_addr(wm * MT + mi, ks, lane, 0)]);
                af[mi][0] = v.x; af[mi][1] = v.y; af[mi][2] = v.z; af[mi][3] = v.w;
            }
#pragma unroll
            for (int ni = 0; ni < NT; ni++) {
                uint2 v = *reinterpret_cast<const uint2*>(
                    &bS[b_addr(wn * NT + ni, ks, lane, 0)]);
                bf[ni][0] = v.x; bf[ni][1] = v.y;
            }
#pragma unroll
            for (int mi = 0; mi < MT; mi++)
#pragma unroll
                for (int ni = 0; ni < NT; ni++)
                    mma_tf32(acc[mi][ni], af[mi], bf[ni]);
        }
        // single sync per iteration (protects buf reuse two iters ahead)
    }

    // ---- epilogue ----
#pragma unroll
    for (int mi = 0; mi < MT; mi++) {
#pragma unroll
        for (int ni = 0; ni < NT; ni++) {
            const int row = m0 + wm * (MT * 16) + mi * 16 + lr;
            const int col = n0 + wn * (NT * 8) + ni * 8 + lc * 2;
            float b0 = bias ? bias[col]     : 0.f;
            float b1 = bias ? bias[col + 1] : 0.f;
            float2 v0 = make_float2(alpha * (acc[mi][ni][0] + b0),
                                    alpha * (acc[mi][ni][1] + b1));
            float2 v1 = make_float2(alpha * (acc[mi][ni][2] + b0),
                                    alpha * (acc[mi][ni][3] + b1));
            *reinterpret_cast<float2*>(C + (long)row * ldc + col)       = v0;
            *reinterpret_cast<float2*>(C + (long)(row + 8) * ldc + col) = v1;
        }
    }
}

// ---------------------------------------------------------------------------
// Row softmax in-place + post-softmax bias add.
// ---------------------------------------------------------------------------
__global__ void softmax_bias_k(float* __restrict__ P,
                               const float* __restrict__ bias)
{
    const long r = blockIdx.x;
    float* row = P + r * (long)SEQ;
    const float* brow = bias + r * (long)SEQ;
    const int tid  = threadIdx.x;
    const int lane = tid & 31;
    const int wid  = tid >> 5;

    __shared__ float sred[8];

    float4 v0 = *reinterpret_cast<const float4*>(row + tid * 4);
    float4 v1 = *reinterpret_cast<const float4*>(row + 1024 + tid * 4);

    float m = fmaxf(fmaxf(fmaxf(v0.x, v0.y), fmaxf(v0.z, v0.w)),
                    fmaxf(fmaxf(v1.x, v1.y), fmaxf(v1.z, v1.w)));
#pragma unroll
    for (int off = 16; off > 0; off >>= 1)
        m = fmaxf(m, __shfl_xor_sync(0xFFFFFFFFu, m, off));
    if (lane == 0) sred[wid] = m;
    __syncthreads();
    float rowmax = sred[0];
#pragma unroll
    for (int j = 1; j < 8; j++) rowmax = fmaxf(rowmax, sred[j]);
    __syncthreads();

    v0.x = __expf(v0.x - rowmax); v0.y = __expf(v0.y - rowmax);
    v0.z = __expf(v0.z - rowmax); v0.w = __expf(v0.w - rowmax);
    v1.x = __expf(v1.x - rowmax); v1.y = __expf(v1.y - rowmax);
    v1.z = __expf(v1.z - rowmax); v1.w = __expf(v1.w - rowmax);
    float s = (v0.x + v0.y + v0.z + v0.w) + (v1.x + v1.y + v1.z + v1.w);
#pragma unroll
    for (int off = 16; off > 0; off >>= 1)
        s += __shfl_xor_sync(0xFFFFFFFFu, s, off);
    if (lane == 0) sred[wid] = s;
    __syncthreads();
    float rowsum = 0.f;
#pragma unroll
    for (int j = 0; j < 8; j++) rowsum += sred[j];
    const float inv = 1.f / rowsum;

    float4 b0 = *reinterpret_cast<const float4*>(brow + tid * 4);
    float4 b1 = *reinterpret_cast<const float4*>(brow + 1024 + tid * 4);
    v0.x = v0.x * inv + b0.x; v0.y = v0.y * inv + b0.y;
    v0.z = v0.z * inv + b0.z; v0.w = v0.w * inv + b0.w;
    v1.x = v1.x * inv + b1.x; v1.y = v1.y * inv + b1.y;
    v1.z = v1.z * inv + b1.z; v1.w = v1.w * inv + b1.w;
    *reinterpret_cast<float4*>(row + tid * 4)        = v0;
    *reinterpret_cast<float4*>(row + 1024 + tid * 4) = v1;
}

// ---------------------------------------------------------------------------
extern "C" void kernel_launch(void* const* d_in, const int* in_sizes, int n_in,
                              void* d_out, int out_size)
{
    const float* q    = (const float*)d_in[0];
    const float* k    = (const float*)d_in[1];
    const float* v    = (const float*)d_in[2];
    const float* bias = (const float*)d_in[3];
    const float* wq   = (const float*)d_in[4];
    const float* bq   = (const float*)d_in[5];
    const float* wk   = (const float*)d_in[6];
    const float* bk   = (const float*)d_in[7];
    const float* wv   = (const float*)d_in[8];
    const float* bv   = (const float*)d_in[9];
    const float* wo   = (const float*)d_in[10];
    const float* bo   = (const float*)d_in[11];
    float* out = (float*)d_out;

    float *qh, *kh, *vh, *P, *x;
    cudaGetSymbolAddress((void**)&qh, g_qh);
    cudaGetSymbolAddress((void**)&kh, g_kh);
    cudaGetSymbolAddress((void**)&vh, g_vh);
    cudaGetSymbolAddress((void**)&P,  g_P);
    cudaGetSymbolAddress((void**)&x,  g_x);

    const float scale = 0.088388347648318447f;  // ATT^-0.5

    // 1-3) projections: [16384,1024] @ [1024,128] + b  (256 CTAs each)
    gemm_tc<64, 128, false><<<dim3(1, (VIEW * SEQ) / 64, 1), 256>>>(
        q, wq, bq, qh, HID, ATT, ATT, 0, 0, 0, HID, scale);
    gemm_tc<64, 128, false><<<dim3(1, (VIEW * SEQ) / 64, 1), 256>>>(
        k, wk, bk, kh, HID, ATT, ATT, 0, 0, 0, HID, 1.f);
    gemm_tc<64, 128, false><<<dim3(1, (VIEW * SEQ) / 64, 1), 256>>>(
        v, wv, bv, vh, HID, ATT, ATT, 0, 0, 0, HID, 1.f);

    // 4) scores: per view  P = qh @ kh^T   [2048,2048]
    gemm_tc<128, 128, true><<<dim3(SEQ / 128, SEQ / 128, VIEW), 256>>>(
        qh, kh, nullptr, P, ATT, ATT, SEQ,
        (long)SEQ * ATT, (long)SEQ * ATT, (long)SEQ * SEQ, ATT, 1.f);

    // 5) softmax rows + post-softmax bias (in-place on P)
    softmax_bias_k<<<VIEW * SEQ, 256>>>(P, bias);

    // 6) x = P @ vh, scattered into [S, V*A]   (256 CTAs)
    gemm_tc<64, 128, false><<<dim3(1, SEQ / 64, VIEW), 256>>>(
        P, vh, nullptr, x, SEQ, ATT, VIEW * ATT,
        (long)SEQ * SEQ, (long)SEQ * ATT, (long)ATT, SEQ, 1.f);

    // 7) out = x @ wo + bo   [2048,1024]   (256 CTAs)
    gemm_tc<64, 128, false><<<dim3(HID / 128, SEQ / 64, 1), 256>>>(
        x, wo, bo, out, VIEW * ATT, HID, HID, 0, 0, 0, VIEW * ATT, 1.f);
}

// round 4
// speedup vs baseline: 2.6458x; 1.1437x over previous
#include <cuda_runtime.h>
#include <cuda_bf16.h>
#include <cstdint>

// ---------------------------------------------------------------------------
// MultiViewSelfAttention: VIEW=8, SEQ=2048, HID=1024, ATT=128
// Round 3: ldmatrix-fragment TF32 GEMMs, STS.128 staging, zero in-loop CVTs
//          (weights pre-transposed+rounded; activations rounded in epilogues).
// ---------------------------------------------------------------------------

#define VIEW 8
#define SEQ  2048
#define HID  1024
#define ATT  128

__device__ float g_qh [VIEW * SEQ * ATT];
__device__ float g_kh [VIEW * SEQ * ATT];
__device__ float g_vh [VIEW * SEQ * ATT];
__device__ float g_vhT[VIEW * ATT * SEQ];
__device__ float g_P  [(long)VIEW * SEQ * SEQ];
__device__ float g_x  [SEQ * (VIEW * ATT)];
__device__ float g_wqT[ATT * HID];
__device__ float g_wkT[ATT * HID];
__device__ float g_wvT[ATT * HID];
__device__ float g_woT[HID * HID];

__device__ __forceinline__ float to_tf32(float x) {
    float y;
    asm("cvt.rna.tf32.f32 %0, %1;" : "=f"(y) : "f"(x));
    return y;
}

__device__ __forceinline__ void mma_tf32(float c[4], const uint32_t a[4],
                                         const uint32_t b[2]) {
    asm volatile(
        "mma.sync.aligned.m16n8k8.row.col.f32.tf32.tf32.f32 "
        "{%0,%1,%2,%3}, {%4,%5,%6,%7}, {%8,%9}, {%0,%1,%2,%3};"
        : "+f"(c[0]), "+f"(c[1]), "+f"(c[2]), "+f"(c[3])
        : "r"(a[0]), "r"(a[1]), "r"(a[2]), "r"(a[3]), "r"(b[0]), "r"(b[1]));
}

__device__ __forceinline__ void ldsm4(uint32_t& r0, uint32_t& r1,
                                      uint32_t& r2, uint32_t& r3,
                                      uint32_t addr) {
    asm volatile("ldmatrix.sync.aligned.m8n8.x4.shared.b16 {%0,%1,%2,%3}, [%4];"
                 : "=r"(r0), "=r"(r1), "=r"(r2), "=r"(r3) : "r"(addr));
}

// ---------------------------------------------------------------------------
// TF32 GEMM (all operands in "BT" form):  C = alpha * (A @ B^T-rows + bias)
//   A: [M,K] row-major.  B: [N,K] row-major.  C[m][n] = sum_k A[m,k]*B[n,k].
//   256 threads = 8 warps as 4(m) x 2(n). BK=16. Tiles: BM=128, BN=128.
//   Smem: row-major tiles in 16B units, swizzle u ^= (row>>1)&3.
//   CVTA: convert A to tf32 while staging (raw fp32 inputs only).
//   RNDOUT: round outputs to tf32 in epilogue.
// ---------------------------------------------------------------------------
template<int BM, int BN, bool CVTA, bool RNDOUT, bool BIAS>
__global__ __launch_bounds__(256, 2)
void gemm_tc(const float* __restrict__ A,
             const float* __restrict__ B,
             const float* __restrict__ bias,
             float* __restrict__ C,
             int lda, int ldb, int ldc,
             long sA, long sB, long sC,
             int K, float alpha)
{
    constexpr int BK = 16;
    constexpr int MT = BM / 64;            // m16 tiles per warp
    constexpr int NT = BN / 16;            // n8 tiles per warp (even)
    constexpr int LA = (BM * BK) / 1024;   // float4 loads/thread
    constexpr int LB = (BN * BK) / 1024;
    constexpr int AUNITS = BM * 4;         // 16B units per A buffer
    constexpr int BUNITS = BN * 4;

    __shared__ float4 aS[2][AUNITS];
    __shared__ float4 bS[2][BUNITS];

    const int tid  = threadIdx.x;
    const int warp = tid >> 5;
    const int lane = tid & 31;
    const int wm   = warp >> 1;            // 0..3
    const int wn   = warp & 1;             // 0..1
    const int lr   = lane >> 2;
    const int lc   = lane & 3;
    const int mi8  = lane >> 3;            // matrix index 0..3
    const int r8   = lane & 7;             // row within matrix

    const int m0 = blockIdx.y * BM;
    const int n0 = blockIdx.x * BN;

    A += (long)blockIdx.z * sA;
    B += (long)blockIdx.z * sB;
    C += (long)blockIdx.z * sC;

    const uint32_t a_sbase = (uint32_t)__cvta_generic_to_shared(&aS[0][0]);
    const uint32_t b_sbase = (uint32_t)__cvta_generic_to_shared(&bS[0][0]);

    // --- per-lane LDSM geometry (precomputed) ---
    // A: matrix mi: row = mtile*16 + (mi&1)*8 + r8 ; unit = 2ks + (mi>>1)
    int a_off[MT], a_swz[MT];
#pragma unroll
    for (int mt = 0; mt < MT; mt++) {
        int arow = (wm * MT + mt) * 16 + ((mi8 & 1) << 3) + r8;
        a_off[mt] = arow * 4;
        a_swz[mt] = (arow >> 1) & 3;
    }
    const int a_uh = mi8 >> 1;
    // B: pair p covers ntiles (2p, 2p+1): matrix mi: ntile = +(mi>>1),
    //    unit = 2ks + (mi&1)
    int b_off[NT / 2], b_swz[NT / 2];
#pragma unroll
    for (int p = 0; p < NT / 2; p++) {
        int brow = (wn * NT + 2 * p + (mi8 >> 1)) * 8 + r8;
        b_off[p] = brow * 4;
        b_swz[p] = (brow >> 1) & 3;
    }
    const int b_uh = mi8 & 1;

    // --- staging geometry ---
    int st_row[LA > LB ? LA : LB], st_u[LA > LB ? LA : LB];
#pragma unroll
    for (int i = 0; i < (LA > LB ? LA : LB); i++) {
        int idx = tid + i * 256;
        st_row[i] = idx >> 2;
        st_u[i]   = (idx & 3) ^ ((st_row[i] >> 1) & 3);
    }

    float acc[MT][NT][4];
#pragma unroll
    for (int i = 0; i < MT; i++)
#pragma unroll
        for (int j = 0; j < NT; j++)
#pragma unroll
            for (int t = 0; t < 4; t++) acc[i][j][t] = 0.f;

    const int NIT = K / BK;
    float4 pa[LA], pb[LB];

    // ---- prologue loads ----
#pragma unroll
    for (int i = 0; i < LA; i++)
        pa[i] = *reinterpret_cast<const float4*>(
            A + (long)(m0 + (tid + i * 256 >> 2)) * lda + ((tid + i * 256) & 3) * 4);
#pragma unroll
    for (int i = 0; i < LB; i++)
        pb[i] = *reinterpret_cast<const float4*>(
            B + (long)(n0 + (tid + i * 256 >> 2)) * ldb + ((tid + i * 256) & 3) * 4);

    for (int it = 0; it < NIT; ++it) {
        const int buf = it & 1;

        // ---- stage into smem (STS.128) ----
#pragma unroll
        for (int i = 0; i < LA; i++) {
            float4 v = pa[i];
            if (CVTA) {
                v.x = to_tf32(v.x); v.y = to_tf32(v.y);
                v.z = to_tf32(v.z); v.w = to_tf32(v.w);
            }
            aS[buf][st_row[i] * 4 + st_u[i]] = v;
        }
#pragma unroll
        for (int i = 0; i < LB; i++)
            bS[buf][st_row[i] * 4 + st_u[i]] = pb[i];
        __syncthreads();

        // ---- prefetch next K-chunk ----
        if (it + 1 < NIT) {
            const int k0 = (it + 1) * BK;
#pragma unroll
            for (int i = 0; i < LA; i++)
                pa[i] = *reinterpret_cast<const float4*>(
                    A + (long)(m0 + (tid + i * 256 >> 2)) * lda + k0 +
                    ((tid + i * 256) & 3) * 4);
#pragma unroll
            for (int i = 0; i < LB; i++)
                pb[i] = *reinterpret_cast<const float4*>(
                    B + (long)(n0 + (tid + i * 256 >> 2)) * ldb + k0 +
                    ((tid + i * 256) & 3) * 4);
        }

        const uint32_t abase = a_sbase + (uint32_t)(buf * AUNITS) * 16u;
        const uint32_t bbase = b_sbase + (uint32_t)(buf * BUNITS) * 16u;

        // ---- MMA over the two k8 steps ----
#pragma unroll
        for (int ks = 0; ks < 2; ks++) {
            uint32_t af[MT][4], bf[NT][2];
#pragma unroll
            for (int mt = 0; mt < MT; mt++) {
                uint32_t addr = abase +
                    (uint32_t)(a_off[mt] + ((2 * ks + a_uh) ^ a_swz[mt])) * 16u;
                ldsm4(af[mt][0], af[mt][1], af[mt][2], af[mt][3], addr);
            }
#pragma unroll
            for (int p = 0; p < NT / 2; p++) {
                uint32_t addr = bbase +
                    (uint32_t)(b_off[p] + ((2 * ks + b_uh) ^ b_swz[p])) * 16u;
                ldsm4(bf[2 * p][0], bf[2 * p][1], bf[2 * p + 1][0],
                      bf[2 * p + 1][1], addr);
            }
#pragma unroll
            for (int mt = 0; mt < MT; mt++)
#pragma unroll
                for (int ni = 0; ni < NT; ni++)
                    mma_tf32(acc[mt][ni], af[mt], bf[ni]);
        }
    }

    // ---- epilogue ----
#pragma unroll
    for (int mt = 0; mt < MT; mt++) {
#pragma unroll
        for (int ni = 0; ni < NT; ni++) {
            const int row = m0 + (wm * MT + mt) * 16 + lr;
            const int col = n0 + wn * (NT * 8) + ni * 8 + lc * 2;
            float b0 = BIAS ? bias[col]     : 0.f;
            float b1 = BIAS ? bias[col + 1] : 0.f;
            float o0 = alpha * (acc[mt][ni][0] + b0);
            float o1 = alpha * (acc[mt][ni][1] + b1);
            float o2 = alpha * (acc[mt][ni][2] + b0);
            float o3 = alpha * (acc[mt][ni][3] + b1);
            if (RNDOUT) {
                o0 = to_tf32(o0); o1 = to_tf32(o1);
                o2 = to_tf32(o2); o3 = to_tf32(o3);
            }
            *reinterpret_cast<float2*>(C + (long)row * ldc + col) =
                make_float2(o0, o1);
            *reinterpret_cast<float2*>(C + (long)(row + 8) * ldc + col) =
                make_float2(o2, o3);
        }
    }
}

// ---------------------------------------------------------------------------
// Tiled transpose [R,C] -> [C,R] per batch z, optional tf32 rounding.
// Block (32,8), grid (C/32, R/32, Z).
// ---------------------------------------------------------------------------
template<bool RND>
__global__ void transpose_k(const float* __restrict__ src,
                            float* __restrict__ dst,
                            int R, int C, long sSrc, long sDst)
{
    __shared__ float t[32][33];
    src += (long)blockIdx.z * sSrc;
    dst += (long)blockIdx.z * sDst;
    const int bx = blockIdx.x * 32;   // col tile in src
    const int by = blockIdx.y * 32;   // row tile in src
    const int x = bx + threadIdx.x;
#pragma unroll
    for (int i = threadIdx.y; i < 32; i += 8) {
        float v = src[(long)(by + i) * C + x];
        t[i][threadIdx.x] = RND ? to_tf32(v) : v;
    }
    __syncthreads();
    const int dx = by + threadIdx.x;
#pragma unroll
    for (int i = threadIdx.y; i < 32; i += 8)
        dst[(long)(bx + i) * R + dx] = t[threadIdx.x][i];
}

// ---------------------------------------------------------------------------
// Row softmax in-place + post-softmax bias add + tf32 rounding of output.
// ---------------------------------------------------------------------------
__global__ void softmax_bias_k(float* __restrict__ P,
                               const float* __restrict__ bias)
{
    const long r = blockIdx.x;
    float* row = P + r * (long)SEQ;
    const float* brow = bias + r * (long)SEQ;
    const int tid  = threadIdx.x;
    const int lane = tid & 31;
    const int wid  = tid >> 5;

    __shared__ float sred[8];

    float4 v0 = *reinterpret_cast<const float4*>(row + tid * 4);
    float4 v1 = *reinterpret_cast<const float4*>(row + 1024 + tid * 4);

    float m = fmaxf(fmaxf(fmaxf(v0.x, v0.y), fmaxf(v0.z, v0.w)),
                    fmaxf(fmaxf(v1.x, v1.y), fmaxf(v1.z, v1.w)));
#pragma unroll
    for (int off = 16; off > 0; off >>= 1)
        m = fmaxf(m, __shfl_xor_sync(0xFFFFFFFFu, m, off));
    if (lane == 0) sred[wid] = m;
    __syncthreads();
    float rowmax = sred[0];
#pragma unroll
    for (int j = 1; j < 8; j++) rowmax = fmaxf(rowmax, sred[j]);
    __syncthreads();

    v0.x = __expf(v0.x - rowmax); v0.y = __expf(v0.y - rowmax);
    v0.z = __expf(v0.z - rowmax); v0.w = __expf(v0.w - rowmax);
    v1.x = __expf(v1.x - rowmax); v1.y = __expf(v1.y - rowmax);
    v1.z = __expf(v1.z - rowmax); v1.w = __expf(v1.w - rowmax);
    float s = (v0.x + v0.y + v0.z + v0.w) + (v1.x + v1.y + v1.z + v1.w);
#pragma unroll
    for (int off = 16; off > 0; off >>= 1)
        s += __shfl_xor_sync(0xFFFFFFFFu, s, off);
    if (lane == 0) sred[wid] = s;
    __syncthreads();
    float rowsum = 0.f;
#pragma unroll
    for (int j = 0; j < 8; j++) rowsum += sred[j];
    const float inv = 1.f / rowsum;

    float4 b0 = *reinterpret_cast<const float4*>(brow + tid * 4);
    float4 b1 = *reinterpret_cast<const float4*>(brow + 1024 + tid * 4);
    v0.x = to_tf32(v0.x * inv + b0.x); v0.y = to_tf32(v0.y * inv + b0.y);
    v0.z = to_tf32(v0.z * inv + b0.z); v0.w = to_tf32(v0.w * inv + b0.w);
    v1.x = to_tf32(v1.x * inv + b1.x); v1.y = to_tf32(v1.y * inv + b1.y);
    v1.z = to_tf32(v1.z * inv + b1.z); v1.w = to_tf32(v1.w * inv + b1.w);
    *reinterpret_cast<float4*>(row + tid * 4)        = v0;
    *reinterpret_cast<float4*>(row + 1024 + tid * 4) = v1;
}

// ---------------------------------------------------------------------------
extern "C" void kernel_launch(void* const* d_in, const int* in_sizes, int n_in,
                              void* d_out, int out_size)
{
    const float* q    = (const float*)d_in[0];
    const float* k    = (const float*)d_in[1];
    const float* v    = (const float*)d_in[2];
    const float* bias = (const float*)d_in[3];
    const float* wq   = (const float*)d_in[4];
    const float* bq   = (const float*)d_in[5];
    const float* wk   = (const float*)d_in[6];
    const float* bk   = (const float*)d_in[7];
    const float* wv   = (const float*)d_in[8];
    const float* bv   = (const float*)d_in[9];
    const float* wo   = (const float*)d_in[10];
    const float* bo   = (const float*)d_in[11];
    float* out = (float*)d_out;

    float *qh, *kh, *vh, *vhT, *P, *x, *wqT, *wkT, *wvT, *woT;
    cudaGetSymbolAddress((void**)&qh,  g_qh);
    cudaGetSymbolAddress((void**)&kh,  g_kh);
    cudaGetSymbolAddress((void**)&vh,  g_vh);
    cudaGetSymbolAddress((void**)&vhT, g_vhT);
    cudaGetSymbolAddress((void**)&P,   g_P);
    cudaGetSymbolAddress((void**)&x,   g_x);
    cudaGetSymbolAddress((void**)&wqT, g_wqT);
    cudaGetSymbolAddress((void**)&wkT, g_wkT);
    cudaGetSymbolAddress((void**)&wvT, g_wvT);
    cudaGetSymbolAddress((void**)&woT, g_woT);

    const float scale = 0.088388347648318447f;  // ATT^-0.5

    // 0) prep: transpose + tf32-round weights
    transpose_k<true><<<dim3(ATT / 32, HID / 32, 1), dim3(32, 8)>>>(
        wq, wqT, HID, ATT, 0, 0);
    transpose_k<true><<<dim3(ATT / 32, HID / 32, 1), dim3(32, 8)>>>(
        wk, wkT, HID, ATT, 0, 0);
    transpose_k<true><<<dim3(ATT / 32, HID / 32, 1), dim3(32, 8)>>>(
        wv, wvT, HID, ATT, 0, 0);
    transpose_k<true><<<dim3(HID / 32, HID / 32, 1), dim3(32, 8)>>>(
        wo, woT, HID, HID, 0, 0);

    // 1-3) projections: [16384,1024] @ wT[128,1024] + b  (CVTA, round out)
    gemm_tc<128, 128, true, true, true>
        <<<dim3(1, (VIEW * SEQ) / 128, 1), 256>>>(
        q, wqT, bq, qh, HID, HID, ATT, 0, 0, 0, HID, scale);
    gemm_tc<128, 128, true, true, true>
        <<<dim3(1, (VIEW * SEQ) / 128, 1), 256>>>(
        k, wkT, bk, kh, HID, HID, ATT, 0, 0, 0, HID, 1.f);
    gemm_tc<128, 128, true, true, true>
        <<<dim3(1, (VIEW * SEQ) / 128, 1), 256>>>(
        v, wvT, bv, vh, HID, HID, ATT, 0, 0, 0, HID, 1.f);

    // 3b) vh -> vhT [V][A][S]
    transpose_k<false><<<dim3(ATT / 32, SEQ / 32, VIEW), dim3(32, 8)>>>(
        vh, vhT, SEQ, ATT, (long)SEQ * ATT, (long)ATT * SEQ);

    // 4) scores: per view  P = qh @ kh^T  [2048,2048] (raw fp32 out)
    gemm_tc<128, 128, false, false, false>
        <<<dim3(SEQ / 128, SEQ / 128, VIEW), 256>>>(
        qh, kh, nullptr, P, ATT, ATT, SEQ,
        (long)SEQ * ATT, (long)SEQ * ATT, (long)SEQ * SEQ, ATT, 1.f);

    // 5) softmax + post-softmax bias + round (in-place on P)
    softmax_bias_k<<<VIEW * SEQ, 256>>>(P, bias);

    // 6) x = P @ vhT^T, scattered into [S, V*A]  (round out)
    gemm_tc<128, 128, false, true, false>
        <<<dim3(1, SEQ / 128, VIEW), 256>>>(
        P, vhT, nullptr, x, SEQ, SEQ, VIEW * ATT,
        (long)SEQ * SEQ, (long)ATT * SEQ, (long)ATT, SEQ, 1.f);

    // 7) out = x @ woT^T + bo   [2048,1024]
    gemm_tc<128, 128, false, false, true>
        <<<dim3(HID / 128, SEQ / 128, 1), 256>>>(
        x, woT, bo, out, VIEW * ATT, HID, HID, 0, 0, 0, VIEW * ATT, 1.f);
}